// round 15
// baseline (speedup 1.0000x reference)
#include <cuda_runtime.h>
#include <cuda_fp16.h>
#include <cstdint>

// GCN: out = spmm(A, relu(spmm(A, x@W1)+b1) @ W2) + b2
// N=50000, E=1.6M, 512 -> 128 -> 64.
// GEMM1: fp16 mma.m16n8k16 + ldmatrix (fp32 in) -> S1 fp16.
// FUSED SpMM1+GEMM2: CSR warp-per-row gather -> bias+ReLU (fp32 regs) ->
//   row @ W2 (smem-staged fp16 W2, scalar FMA hidden under gather stalls)
//   -> S2 fp16. No H round-trip, no separate GEMM2 kernel.
// SpMM2: CSR warp-per-row, fp16 gather -> fp32 out.
// Overlap: CSR build || GEMM1 (graph fork/join).
// edge_index is int32 on device (JAX default config downcasts int64).

#define IN_DIM  512
#define HID_DIM 128
#define OUT_DIM 64
#define N_MAX   50000
#define E_MAX   1600000

__device__ __half g_S1[(size_t)N_MAX * HID_DIM];  // x @ W1   (fp16)
__device__ __half g_S2[(size_t)N_MAX * OUT_DIM];  // relu(H) @ W2 (fp16)

// CSR scratch
__device__ int  g_rowptr[N_MAX + 1];
__device__ int  g_rowaux[N_MAX];
__device__ int2 g_edges [E_MAX];      // {colidx, weight-as-int}

// ---------------------------------------------------------------------------
// GEMM1: S1[M,128] = x[M,512] @ W1[512,128], fp16 mma.m16n8k16, fp32 accum.
// Block tile 128x128, BK=32, 8 warps (4 M x 2 N). LDH=40 halfs -> conflict-free
// ldmatrix (granule walk 5*row mod 8).
// ---------------------------------------------------------------------------
__global__ __launch_bounds__(256) void gemm1_mma_f16(
        const float* __restrict__ A, const float* __restrict__ W,
        __half* __restrict__ C, int M) {
    constexpr int BM = 128, BN = 128, BK = 32, LDH = 40;
    __shared__ __half sA[BM * LDH];
    __shared__ __half sB[BN * LDH];

    const int tid  = threadIdx.x;
    const int wid  = tid >> 5;
    const int lane = tid & 31;
    const int gid  = lane >> 2;
    const int tig  = lane & 3;
    const int warpM = (wid & 3) * 32;
    const int warpN = (wid >> 2) * 64;
    const int rowBase = blockIdx.x * BM;

    const int a_row = ((lane >> 3) & 1) * 8 + (lane & 7);
    const int a_koff = (lane >> 4) * 8;
    const int b_n   = (lane >> 4) * 8 + (lane & 7);
    const int b_koff = ((lane >> 3) & 1) * 8;

    const uint32_t sA_u = (uint32_t)__cvta_generic_to_shared(sA);
    const uint32_t sB_u = (uint32_t)__cvta_generic_to_shared(sB);

    float acc[2][8][4];
    #pragma unroll
    for (int a = 0; a < 2; a++)
        #pragma unroll
        for (int b = 0; b < 8; b++)
            #pragma unroll
            for (int c = 0; c < 4; c++) acc[a][b][c] = 0.f;

    for (int k0 = 0; k0 < IN_DIM; k0 += BK) {
        #pragma unroll
        for (int i = 0; i < 4; i++) {
            int f = tid + i * 256;
            int r = f >> 3, q = f & 7;
            int m = rowBase + r;
            float4 v = make_float4(0.f, 0.f, 0.f, 0.f);
            if (m < M) v = *(const float4*)(A + (size_t)m * IN_DIM + k0 + q * 4);
            __half2 h0 = __floats2half2_rn(v.x, v.y);
            __half2 h1 = __floats2half2_rn(v.z, v.w);
            uint2 u;
            u.x = *(uint32_t*)&h0; u.y = *(uint32_t*)&h1;
            *(uint2*)&sA[r * LDH + q * 4] = u;
        }
        #pragma unroll
        for (int i = 0; i < 8; i++) {
            int f = tid + i * 256;
            int n = f & (BN - 1), kp = f >> 7;
            float w0 = W[(size_t)(k0 + 2 * kp) * BN + n];
            float w1 = W[(size_t)(k0 + 2 * kp + 1) * BN + n];
            *(__half2*)&sB[n * LDH + 2 * kp] = __floats2half2_rn(w0, w1);
        }
        __syncthreads();

        #pragma unroll
        for (int ks = 0; ks < 2; ks++) {
            uint32_t af[2][4];
            #pragma unroll
            for (int mt = 0; mt < 2; mt++) {
                uint32_t addr = sA_u +
                    ((warpM + mt * 16 + a_row) * LDH + ks * 16 + a_koff) * 2;
                asm volatile(
                    "ldmatrix.sync.aligned.m8n8.x4.shared.b16 {%0,%1,%2,%3}, [%4];"
                    : "=r"(af[mt][0]), "=r"(af[mt][1]),
                      "=r"(af[mt][2]), "=r"(af[mt][3])
                    : "r"(addr));
            }
            uint32_t bf[4][4];
            #pragma unroll
            for (int ntp = 0; ntp < 4; ntp++) {
                uint32_t addr = sB_u +
                    ((warpN + ntp * 16 + b_n) * LDH + ks * 16 + b_koff) * 2;
                asm volatile(
                    "ldmatrix.sync.aligned.m8n8.x4.shared.b16 {%0,%1,%2,%3}, [%4];"
                    : "=r"(bf[ntp][0]), "=r"(bf[ntp][1]),
                      "=r"(bf[ntp][2]), "=r"(bf[ntp][3])
                    : "r"(addr));
            }
            #pragma unroll
            for (int mt = 0; mt < 2; mt++)
                #pragma unroll
                for (int ntp = 0; ntp < 4; ntp++)
                    #pragma unroll
                    for (int hh = 0; hh < 2; hh++) {
                        int nt = ntp * 2 + hh;
                        asm volatile(
                            "mma.sync.aligned.m16n8k16.row.col.f32.f16.f16.f32 "
                            "{%0,%1,%2,%3}, {%4,%5,%6,%7}, {%8,%9}, {%0,%1,%2,%3};"
                            : "+f"(acc[mt][nt][0]), "+f"(acc[mt][nt][1]),
                              "+f"(acc[mt][nt][2]), "+f"(acc[mt][nt][3])
                            : "r"(af[mt][0]), "r"(af[mt][1]),
                              "r"(af[mt][2]), "r"(af[mt][3]),
                              "r"(bf[ntp][hh * 2 + 0]), "r"(bf[ntp][hh * 2 + 1]));
                    }
        }
        __syncthreads();
    }

    #pragma unroll
    for (int mt = 0; mt < 2; mt++)
        #pragma unroll
        for (int rr = 0; rr < 2; rr++) {
            int m = rowBase + warpM + mt * 16 + rr * 8 + gid;
            if (m < M) {
                __half* cp = C + (size_t)m * BN + warpN;
                #pragma unroll
                for (int nt = 0; nt < 8; nt++)
                    *(__half2*)(cp + nt * 8 + 2 * tig) =
                        __floats2half2_rn(acc[mt][nt][rr * 2 + 0],
                                          acc[mt][nt][rr * 2 + 1]);
            }
        }
}

// ---------------------------------------------------------------------------
// CSR build
// ---------------------------------------------------------------------------
__global__ void zero_counts_kernel(int* __restrict__ cnt, int n) {
    int i = blockIdx.x * blockDim.x + threadIdx.x;
    if (i < n) cnt[i] = 0;
}

__global__ void hist_kernel(const int* __restrict__ rows, int* __restrict__ cnt, int E) {
    int e = blockIdx.x * blockDim.x + threadIdx.x;
    if (e < E) atomicAdd(&cnt[rows[e]], 1);
}

__global__ __launch_bounds__(1024) void scan_kernel(
        int* __restrict__ cnt_and_cursor, int* __restrict__ rowptr, int N, int E) {
    __shared__ int part[1024];
    const int t = threadIdx.x;
    const int chunk = (N + 1023) / 1024;
    const int lo = t * chunk;
    const int hi = min(lo + chunk, N);
    int s = 0;
    for (int i = lo; i < hi; i++) s += cnt_and_cursor[i];
    part[t] = s;
    __syncthreads();
    #pragma unroll
    for (int off = 1; off < 1024; off <<= 1) {
        int v = (t >= off) ? part[t - off] : 0;
        __syncthreads();
        part[t] += v;
        __syncthreads();
    }
    int base = (t == 0) ? 0 : part[t - 1];
    for (int i = lo; i < hi; i++) {
        int c = cnt_and_cursor[i];
        rowptr[i] = base;
        cnt_and_cursor[i] = base;
        base += c;
    }
    if (t == 0) rowptr[N] = E;
}

__global__ void scatter_kernel(const int* __restrict__ rows,
                               const int* __restrict__ cols,
                               const float* __restrict__ ew,
                               int* __restrict__ cursor,
                               int2* __restrict__ edges, int E) {
    int e = blockIdx.x * blockDim.x + threadIdx.x;
    if (e >= E) return;
    int r = rows[e];
    int pos = atomicAdd(&cursor[r], 1);
    edges[pos] = make_int2(cols[e], __float_as_int(ew[e]));
}

// ---------------------------------------------------------------------------
// FUSED SpMM1 + GEMM2: one warp per row.
//   acc = b1 + sum_j w_j * S1[col_j]     (fp16 gather, fp32 accum)
//   h   = relu(acc)                       -> smem (fp32)
//   S2[row][c] = sum_k h[k] * W2[k][c]    (smem fp16 W2, 2 cols per lane)
// 512 threads = 16 warps = 16 rows per block.
// ---------------------------------------------------------------------------
__global__ __launch_bounds__(512) void spmm1_gemm2_fused(
        const int* __restrict__ rowptr,
        const int2* __restrict__ edges,
        const __half* __restrict__ src,        // S1 [N,128] fp16
        const float* __restrict__ b1,
        const float* __restrict__ W2,          // [128,64] fp32
        __half* __restrict__ S2, int N) {
    constexpr int D = 128;
    __shared__ __half sW2[HID_DIM * OUT_DIM];  // 16 KB, [k][c] fp16
    __shared__ float  sH[16][HID_DIM];         // 8 KB, one row per warp

    const int tid  = threadIdx.x;
    const int wid  = tid >> 5;
    const int lane = tid & 31;
    const int row  = blockIdx.x * 16 + wid;

    // Stage W2 -> fp16 smem: 8192 floats / 512 threads = 4 x float4 each.
    #pragma unroll
    for (int i = 0; i < 4; i++) {
        int f = (tid + i * 512) * 4;           // float index, coalesced
        float4 v = *(const float4*)(W2 + f);
        __half2 h0 = __floats2half2_rn(v.x, v.y);
        __half2 h1 = __floats2half2_rn(v.z, v.w);
        uint2 u;
        u.x = *(uint32_t*)&h0; u.y = *(uint32_t*)&h1;
        *(uint2*)&sW2[f] = u;
    }

    // ---- gather phase (no smem use) ----
    float acc[4] = {0.f, 0.f, 0.f, 0.f};
    if (row < N) {
        #pragma unroll
        for (int v = 0; v < 4; v++) acc[v] = b1[lane * 4 + v];
        const int s = rowptr[row];
        const int e = rowptr[row + 1];
        int j = s;
        for (; j + 2 <= e; j += 2) {
            int2 e0 = edges[j], e1 = edges[j + 1];
            float w0 = __int_as_float(e0.y), w1 = __int_as_float(e1.y);
            uint2 u0 = *(const uint2*)(src + (size_t)e0.x * D + lane * 4);
            uint2 u1 = *(const uint2*)(src + (size_t)e1.x * D + lane * 4);
            float2 a0 = __half22float2(*(const __half2*)&u0.x);
            float2 a1 = __half22float2(*(const __half2*)&u0.y);
            float2 c0 = __half22float2(*(const __half2*)&u1.x);
            float2 c1 = __half22float2(*(const __half2*)&u1.y);
            acc[0] = fmaf(w0, a0.x, fmaf(w1, c0.x, acc[0]));
            acc[1] = fmaf(w0, a0.y, fmaf(w1, c0.y, acc[1]));
            acc[2] = fmaf(w0, a1.x, fmaf(w1, c1.x, acc[2]));
            acc[3] = fmaf(w0, a1.y, fmaf(w1, c1.y, acc[3]));
        }
        if (j < e) {
            int2 e0 = edges[j];
            float w0 = __int_as_float(e0.y);
            uint2 u0 = *(const uint2*)(src + (size_t)e0.x * D + lane * 4);
            float2 a0 = __half22float2(*(const __half2*)&u0.x);
            float2 a1 = __half22float2(*(const __half2*)&u0.y);
            acc[0] = fmaf(w0, a0.x, acc[0]);
            acc[1] = fmaf(w0, a0.y, acc[1]);
            acc[2] = fmaf(w0, a1.x, acc[2]);
            acc[3] = fmaf(w0, a1.y, acc[3]);
        }
    }

    // ReLU -> park H row in smem (fp32)
    #pragma unroll
    for (int v = 0; v < 4; v++) acc[v] = fmaxf(acc[v], 0.f);
    *(float4*)&sH[wid][lane * 4] = make_float4(acc[0], acc[1], acc[2], acc[3]);

    __syncthreads();   // sW2 staging complete; sH row visible within warp anyway

    // ---- GEMM2 phase: lane computes output cols 2*lane, 2*lane+1 ----
    if (row < N) {
        float s0 = 0.f, s1 = 0.f;
        const float* hrow = sH[wid];
        #pragma unroll 8
        for (int k = 0; k < HID_DIM; k++) {
            float h = hrow[k];                               // LDS broadcast
            float2 w = __half22float2(*(const __half2*)&sW2[k * OUT_DIM + 2 * lane]);
            s0 = fmaf(h, w.x, s0);
            s1 = fmaf(h, w.y, s1);
        }
        *(__half2*)(S2 + (size_t)row * OUT_DIM + 2 * lane) =
            __floats2half2_rn(s0, s1);
    }
}

// ---------------------------------------------------------------------------
// SpMM2: warp per row, D=64 fp16 payload; dst = bias + sum in fp32.
// ---------------------------------------------------------------------------
__global__ void csr_spmm_h_f_kernel(const int* __restrict__ rowptr,
                                    const int2* __restrict__ edges,
                                    const __half* __restrict__ src,
                                    const float* __restrict__ bias,
                                    float* __restrict__ dst, int N) {
    constexpr int D = 64;
    const int lane = threadIdx.x & 31;
    const int row  = blockIdx.x * (blockDim.x >> 5) + (threadIdx.x >> 5);
    if (row >= N) return;

    const int s = rowptr[row];
    const int e = rowptr[row + 1];

    float acc[2];
    acc[0] = bias[lane * 2 + 0];
    acc[1] = bias[lane * 2 + 1];

    int j = s;
    for (; j + 2 <= e; j += 2) {
        int2 e0 = edges[j], e1 = edges[j + 1];
        float w0 = __int_as_float(e0.y), w1 = __int_as_float(e1.y);
        float2 a0 = __half22float2(*(const __half2*)(src + (size_t)e0.x * D + lane * 2));
        float2 c0 = __half22float2(*(const __half2*)(src + (size_t)e1.x * D + lane * 2));
        acc[0] = fmaf(w0, a0.x, fmaf(w1, c0.x, acc[0]));
        acc[1] = fmaf(w0, a0.y, fmaf(w1, c0.y, acc[1]));
    }
    if (j < e) {
        int2 e0 = edges[j];
        float w0 = __int_as_float(e0.y);
        float2 a0 = __half22float2(*(const __half2*)(src + (size_t)e0.x * D + lane * 2));
        acc[0] = fmaf(w0, a0.x, acc[0]);
        acc[1] = fmaf(w0, a0.y, acc[1]);
    }

    *(float2*)(dst + (size_t)row * D + lane * 2) = make_float2(acc[0], acc[1]);
}

// ---------------------------------------------------------------------------
extern "C" void kernel_launch(void* const* d_in, const int* in_sizes, int n_in,
                              void* d_out, int out_size) {
    const float* x  = (const float*)d_in[0];
    const int*   ei = (const int*)d_in[1];     // [2, E] int32
    const float* ew = (const float*)d_in[2];
    const float* W1 = (const float*)d_in[3];
    const float* b1 = (const float*)d_in[4];
    const float* W2 = (const float*)d_in[5];
    const float* b2 = (const float*)d_in[6];
    float* out = (float*)d_out;

    const int M = in_sizes[0] / IN_DIM;   // 50000
    const int E = in_sizes[2];            // 1600000

    __half *S1, *S2;
    int *rowptr, *rowaux;
    int2 *edges;
    cudaGetSymbolAddress((void**)&S1, g_S1);
    cudaGetSymbolAddress((void**)&S2, g_S2);
    cudaGetSymbolAddress((void**)&rowptr, g_rowptr);
    cudaGetSymbolAddress((void**)&rowaux, g_rowaux);
    cudaGetSymbolAddress((void**)&edges,  g_edges);

    const int* e_rows = ei;
    const int* e_cols = ei + E;

    static cudaStream_t s_build = nullptr;
    static cudaEvent_t  ev_fork = nullptr, ev_join = nullptr;
    if (s_build == nullptr) {
        cudaStreamCreateWithFlags(&s_build, cudaStreamNonBlocking);
        cudaEventCreateWithFlags(&ev_fork, cudaEventDisableTiming);
        cudaEventCreateWithFlags(&ev_join, cudaEventDisableTiming);
    }

    // ---- fork: CSR build on side stream, GEMM1 on main ----
    cudaEventRecord(ev_fork, 0);
    cudaStreamWaitEvent(s_build, ev_fork, 0);

    zero_counts_kernel<<<(M + 255) / 256, 256, 0, s_build>>>(rowaux, M);
    hist_kernel<<<(E + 255) / 256, 256, 0, s_build>>>(e_rows, rowaux, E);
    scan_kernel<<<1, 1024, 0, s_build>>>(rowaux, rowptr, M, E);
    scatter_kernel<<<(E + 255) / 256, 256, 0, s_build>>>(e_rows, e_cols, ew,
                                                         rowaux, edges, E);
    cudaEventRecord(ev_join, s_build);

    // GEMM1: S1 = x @ W1 (fp16 mma) — concurrent with CSR build
    gemm1_mma_f16<<<(M + 127) / 128, 256>>>(x, W1, S1, M);

    // ---- join ----
    cudaStreamWaitEvent(0, ev_join, 0);

    // Fused SpMM1 + GEMM2: S2 = relu(A @ S1 + b1) @ W2
    spmm1_gemm2_fused<<<(M + 15) / 16, 512>>>(rowptr, edges, S1, b1, W2, S2, M);

    // SpMM2: out = A @ S2 + b2 (fp32 out)
    csr_spmm_h_f_kernel<<<(M + 7) / 8, 256>>>(rowptr, edges, S2, b2, out, M);
}

// round 17
// speedup vs baseline: 1.6295x; 1.6295x over previous
#include <cuda_runtime.h>
#include <cuda_fp16.h>
#include <cstdint>

// GCN: out = spmm(A, relu(spmm(A, x@W1)+b1) @ W2) + b2
// N=50000, E=1.6M, 512 -> 128 -> 64.
// GEMM1: fp16 mma.m16n8k16 + ldmatrix (fp32 in) -> S1 fp16.
// SpMM1: CSR warp-per-row, fp16 gather, fused bias+ReLU -> H fp16.
// GEMM2: fp16 mma.m16n8k16 + ldmatrix (fp16 in)  -> S2 fp16.
// SpMM2: CSR warp-per-row, fp16 gather -> fp32 out.
// Overlap: CSR build || GEMM1. Build hist/scatter: 2 edges/thread (MLP=2).
// edge_index is int32 on device (JAX default config downcasts int64).

#define IN_DIM  512
#define HID_DIM 128
#define OUT_DIM 64
#define N_MAX   50000
#define E_MAX   1600000

__device__ __half g_S1[(size_t)N_MAX * HID_DIM];  // x @ W1              (fp16)
__device__ __half g_H [(size_t)N_MAX * HID_DIM];  // relu(spmm1 + b1)   (fp16)
__device__ __half g_S2[(size_t)N_MAX * OUT_DIM];  // H @ W2             (fp16)

// CSR scratch
__device__ int  g_rowptr[N_MAX + 1];
__device__ int  g_rowaux[N_MAX];
__device__ int2 g_edges [E_MAX];      // {colidx, weight-as-int}

// ---------------------------------------------------------------------------
// GEMM1: S1[M,128] = x[M,512] @ W1[512,128], fp16 mma.m16n8k16, fp32 accum.
// Block tile 128x128, BK=32, 8 warps (4 M x 2 N). LDH=40 -> conflict-free
// ldmatrix.
// ---------------------------------------------------------------------------
__global__ __launch_bounds__(256) void gemm1_mma_f16(
        const float* __restrict__ A, const float* __restrict__ W,
        __half* __restrict__ C, int M) {
    constexpr int BM = 128, BN = 128, BK = 32, LDH = 40;
    __shared__ __half sA[BM * LDH];
    __shared__ __half sB[BN * LDH];

    const int tid  = threadIdx.x;
    const int wid  = tid >> 5;
    const int lane = tid & 31;
    const int gid  = lane >> 2;
    const int tig  = lane & 3;
    const int warpM = (wid & 3) * 32;
    const int warpN = (wid >> 2) * 64;
    const int rowBase = blockIdx.x * BM;

    const int a_row = ((lane >> 3) & 1) * 8 + (lane & 7);
    const int a_koff = (lane >> 4) * 8;
    const int b_n   = (lane >> 4) * 8 + (lane & 7);
    const int b_koff = ((lane >> 3) & 1) * 8;

    const uint32_t sA_u = (uint32_t)__cvta_generic_to_shared(sA);
    const uint32_t sB_u = (uint32_t)__cvta_generic_to_shared(sB);

    float acc[2][8][4];
    #pragma unroll
    for (int a = 0; a < 2; a++)
        #pragma unroll
        for (int b = 0; b < 8; b++)
            #pragma unroll
            for (int c = 0; c < 4; c++) acc[a][b][c] = 0.f;

    for (int k0 = 0; k0 < IN_DIM; k0 += BK) {
        #pragma unroll
        for (int i = 0; i < 4; i++) {
            int f = tid + i * 256;
            int r = f >> 3, q = f & 7;
            int m = rowBase + r;
            float4 v = make_float4(0.f, 0.f, 0.f, 0.f);
            if (m < M) v = *(const float4*)(A + (size_t)m * IN_DIM + k0 + q * 4);
            __half2 h0 = __floats2half2_rn(v.x, v.y);
            __half2 h1 = __floats2half2_rn(v.z, v.w);
            uint2 u;
            u.x = *(uint32_t*)&h0; u.y = *(uint32_t*)&h1;
            *(uint2*)&sA[r * LDH + q * 4] = u;
        }
        #pragma unroll
        for (int i = 0; i < 8; i++) {
            int f = tid + i * 256;
            int n = f & (BN - 1), kp = f >> 7;
            float w0 = W[(size_t)(k0 + 2 * kp) * BN + n];
            float w1 = W[(size_t)(k0 + 2 * kp + 1) * BN + n];
            *(__half2*)&sB[n * LDH + 2 * kp] = __floats2half2_rn(w0, w1);
        }
        __syncthreads();

        #pragma unroll
        for (int ks = 0; ks < 2; ks++) {
            uint32_t af[2][4];
            #pragma unroll
            for (int mt = 0; mt < 2; mt++) {
                uint32_t addr = sA_u +
                    ((warpM + mt * 16 + a_row) * LDH + ks * 16 + a_koff) * 2;
                asm volatile(
                    "ldmatrix.sync.aligned.m8n8.x4.shared.b16 {%0,%1,%2,%3}, [%4];"
                    : "=r"(af[mt][0]), "=r"(af[mt][1]),
                      "=r"(af[mt][2]), "=r"(af[mt][3])
                    : "r"(addr));
            }
            uint32_t bf[4][4];
            #pragma unroll
            for (int ntp = 0; ntp < 4; ntp++) {
                uint32_t addr = sB_u +
                    ((warpN + ntp * 16 + b_n) * LDH + ks * 16 + b_koff) * 2;
                asm volatile(
                    "ldmatrix.sync.aligned.m8n8.x4.shared.b16 {%0,%1,%2,%3}, [%4];"
                    : "=r"(bf[ntp][0]), "=r"(bf[ntp][1]),
                      "=r"(bf[ntp][2]), "=r"(bf[ntp][3])
                    : "r"(addr));
            }
            #pragma unroll
            for (int mt = 0; mt < 2; mt++)
                #pragma unroll
                for (int ntp = 0; ntp < 4; ntp++)
                    #pragma unroll
                    for (int hh = 0; hh < 2; hh++) {
                        int nt = ntp * 2 + hh;
                        asm volatile(
                            "mma.sync.aligned.m16n8k16.row.col.f32.f16.f16.f32 "
                            "{%0,%1,%2,%3}, {%4,%5,%6,%7}, {%8,%9}, {%0,%1,%2,%3};"
                            : "+f"(acc[mt][nt][0]), "+f"(acc[mt][nt][1]),
                              "+f"(acc[mt][nt][2]), "+f"(acc[mt][nt][3])
                            : "r"(af[mt][0]), "r"(af[mt][1]),
                              "r"(af[mt][2]), "r"(af[mt][3]),
                              "r"(bf[ntp][hh * 2 + 0]), "r"(bf[ntp][hh * 2 + 1]));
                    }
        }
        __syncthreads();
    }

    #pragma unroll
    for (int mt = 0; mt < 2; mt++)
        #pragma unroll
        for (int rr = 0; rr < 2; rr++) {
            int m = rowBase + warpM + mt * 16 + rr * 8 + gid;
            if (m < M) {
                __half* cp = C + (size_t)m * BN + warpN;
                #pragma unroll
                for (int nt = 0; nt < 8; nt++)
                    *(__half2*)(cp + nt * 8 + 2 * tig) =
                        __floats2half2_rn(acc[mt][nt][rr * 2 + 0],
                                          acc[mt][nt][rr * 2 + 1]);
            }
        }
}

// ---------------------------------------------------------------------------
// GEMM2: S2[M,64] = H[M,128] @ W2[128,64], fp16 in (H), fp16 mma, fp32 accum.
// Block tile 128x64, BK=32, 8 warps (4 M x 2 N), warp tile 32x32.
// ---------------------------------------------------------------------------
__global__ __launch_bounds__(256) void gemm2_mma_f16(
        const __half* __restrict__ A, const float* __restrict__ W,
        __half* __restrict__ C, int M) {
    constexpr int BM = 128, BN = 64, BK = 32, K = HID_DIM, LDH = 40;
    __shared__ __half sA[BM * LDH];
    __shared__ __half sB[BN * LDH];

    const int tid  = threadIdx.x;
    const int wid  = tid >> 5;
    const int lane = tid & 31;
    const int gid  = lane >> 2;
    const int tig  = lane & 3;
    const int warpM = (wid & 3) * 32;
    const int warpN = (wid >> 2) * 32;
    const int rowBase = blockIdx.x * BM;

    const int a_row = ((lane >> 3) & 1) * 8 + (lane & 7);
    const int a_koff = (lane >> 4) * 8;
    const int b_n   = (lane >> 4) * 8 + (lane & 7);
    const int b_koff = ((lane >> 3) & 1) * 8;

    const uint32_t sA_u = (uint32_t)__cvta_generic_to_shared(sA);
    const uint32_t sB_u = (uint32_t)__cvta_generic_to_shared(sB);

    float acc[2][4][4];
    #pragma unroll
    for (int a = 0; a < 2; a++)
        #pragma unroll
        for (int b = 0; b < 4; b++)
            #pragma unroll
            for (int c = 0; c < 4; c++) acc[a][b][c] = 0.f;

    for (int k0 = 0; k0 < K; k0 += BK) {
        #pragma unroll
        for (int i = 0; i < 2; i++) {
            int f = tid + i * 256;
            int r = f >> 2, q = f & 3;
            int m = rowBase + r;
            uint4 u = make_uint4(0u, 0u, 0u, 0u);
            if (m < M) u = *(const uint4*)(A + (size_t)m * K + k0 + q * 8);
            *(uint4*)&sA[r * LDH + q * 8] = u;
        }
        #pragma unroll
        for (int i = 0; i < 4; i++) {
            int f = tid + i * 256;
            int n = f & (BN - 1), kp = f >> 6;
            float w0 = W[(size_t)(k0 + 2 * kp) * BN + n];
            float w1 = W[(size_t)(k0 + 2 * kp + 1) * BN + n];
            *(__half2*)&sB[n * LDH + 2 * kp] = __floats2half2_rn(w0, w1);
        }
        __syncthreads();

        #pragma unroll
        for (int ks = 0; ks < 2; ks++) {
            uint32_t af[2][4];
            #pragma unroll
            for (int mt = 0; mt < 2; mt++) {
                uint32_t addr = sA_u +
                    ((warpM + mt * 16 + a_row) * LDH + ks * 16 + a_koff) * 2;
                asm volatile(
                    "ldmatrix.sync.aligned.m8n8.x4.shared.b16 {%0,%1,%2,%3}, [%4];"
                    : "=r"(af[mt][0]), "=r"(af[mt][1]),
                      "=r"(af[mt][2]), "=r"(af[mt][3])
                    : "r"(addr));
            }
            uint32_t bf[2][4];
            #pragma unroll
            for (int ntp = 0; ntp < 2; ntp++) {
                uint32_t addr = sB_u +
                    ((warpN + ntp * 16 + b_n) * LDH + ks * 16 + b_koff) * 2;
                asm volatile(
                    "ldmatrix.sync.aligned.m8n8.x4.shared.b16 {%0,%1,%2,%3}, [%4];"
                    : "=r"(bf[ntp][0]), "=r"(bf[ntp][1]),
                      "=r"(bf[ntp][2]), "=r"(bf[ntp][3])
                    : "r"(addr));
            }
            #pragma unroll
            for (int mt = 0; mt < 2; mt++)
                #pragma unroll
                for (int ntp = 0; ntp < 2; ntp++)
                    #pragma unroll
                    for (int hh = 0; hh < 2; hh++) {
                        int nt = ntp * 2 + hh;
                        asm volatile(
                            "mma.sync.aligned.m16n8k16.row.col.f32.f16.f16.f32 "
                            "{%0,%1,%2,%3}, {%4,%5,%6,%7}, {%8,%9}, {%0,%1,%2,%3};"
                            : "+f"(acc[mt][nt][0]), "+f"(acc[mt][nt][1]),
                              "+f"(acc[mt][nt][2]), "+f"(acc[mt][nt][3])
                            : "r"(af[mt][0]), "r"(af[mt][1]),
                              "r"(af[mt][2]), "r"(af[mt][3]),
                              "r"(bf[ntp][hh * 2 + 0]), "r"(bf[ntp][hh * 2 + 1]));
                    }
        }
        __syncthreads();
    }

    #pragma unroll
    for (int mt = 0; mt < 2; mt++)
        #pragma unroll
        for (int rr = 0; rr < 2; rr++) {
            int m = rowBase + warpM + mt * 16 + rr * 8 + gid;
            if (m < M) {
                __half* cp = C + (size_t)m * BN + warpN;
                #pragma unroll
                for (int nt = 0; nt < 4; nt++)
                    *(__half2*)(cp + nt * 8 + 2 * tig) =
                        __floats2half2_rn(acc[mt][nt][rr * 2 + 0],
                                          acc[mt][nt][rr * 2 + 1]);
            }
        }
}

// ---------------------------------------------------------------------------
// CSR build (hist/scatter: 2 edges per thread for MLP)
// ---------------------------------------------------------------------------
__global__ void zero_counts_kernel(int* __restrict__ cnt, int n) {
    int i = blockIdx.x * blockDim.x + threadIdx.x;
    if (i < n) cnt[i] = 0;
}

__global__ void hist_kernel(const int* __restrict__ rows, int* __restrict__ cnt, int E) {
    int t = blockIdx.x * blockDim.x + threadIdx.x;
    int e = t * 2;
    if (e + 1 < E) {
        int2 r = *(const int2*)(rows + e);
        atomicAdd(&cnt[r.x], 1);
        atomicAdd(&cnt[r.y], 1);
    } else if (e < E) {
        atomicAdd(&cnt[rows[e]], 1);
    }
}

__global__ __launch_bounds__(1024) void scan_kernel(
        int* __restrict__ cnt_and_cursor, int* __restrict__ rowptr, int N, int E) {
    __shared__ int part[1024];
    const int t = threadIdx.x;
    const int chunk = (N + 1023) / 1024;
    const int lo = t * chunk;
    const int hi = min(lo + chunk, N);
    int s = 0;
    for (int i = lo; i < hi; i++) s += cnt_and_cursor[i];
    part[t] = s;
    __syncthreads();
    #pragma unroll
    for (int off = 1; off < 1024; off <<= 1) {
        int v = (t >= off) ? part[t - off] : 0;
        __syncthreads();
        part[t] += v;
        __syncthreads();
    }
    int base = (t == 0) ? 0 : part[t - 1];
    for (int i = lo; i < hi; i++) {
        int c = cnt_and_cursor[i];
        rowptr[i] = base;
        cnt_and_cursor[i] = base;
        base += c;
    }
    if (t == 0) rowptr[N] = E;
}

__global__ void scatter_kernel(const int* __restrict__ rows,
                               const int* __restrict__ cols,
                               const float* __restrict__ ew,
                               int* __restrict__ cursor,
                               int2* __restrict__ edges, int E) {
    int t = blockIdx.x * blockDim.x + threadIdx.x;
    int e = t * 2;
    if (e + 1 < E) {
        int2   r = *(const int2*)(rows + e);
        int2   c = *(const int2*)(cols + e);
        float2 w = *(const float2*)(ew + e);
        int p0 = atomicAdd(&cursor[r.x], 1);
        int p1 = atomicAdd(&cursor[r.y], 1);
        edges[p0] = make_int2(c.x, __float_as_int(w.x));
        edges[p1] = make_int2(c.y, __float_as_int(w.y));
    } else if (e < E) {
        int p = atomicAdd(&cursor[rows[e]], 1);
        edges[p] = make_int2(cols[e], __float_as_int(ew[e]));
    }
}

// ---------------------------------------------------------------------------
// SpMM1: warp per row, D=128 fp16 payload; dst = relu(bias + sum) in fp16.
// ---------------------------------------------------------------------------
__global__ void csr_spmm_h_relu_kernel(const int* __restrict__ rowptr,
                                       const int2* __restrict__ edges,
                                       const __half* __restrict__ src,
                                       const float* __restrict__ bias,
                                       __half* __restrict__ dst, int N) {
    constexpr int D = 128;
    const int lane = threadIdx.x & 31;
    const int row  = blockIdx.x * (blockDim.x >> 5) + (threadIdx.x >> 5);
    if (row >= N) return;

    const int s = rowptr[row];
    const int e = rowptr[row + 1];

    float acc[4];
    #pragma unroll
    for (int v = 0; v < 4; v++) acc[v] = bias[lane * 4 + v];

    int j = s;
    for (; j + 2 <= e; j += 2) {
        int2 e0 = edges[j], e1 = edges[j + 1];
        float w0 = __int_as_float(e0.y), w1 = __int_as_float(e1.y);
        uint2 u0 = *(const uint2*)(src + (size_t)e0.x * D + lane * 4);
        uint2 u1 = *(const uint2*)(src + (size_t)e1.x * D + lane * 4);
        float2 a0 = __half22float2(*(const __half2*)&u0.x);
        float2 a1 = __half22float2(*(const __half2*)&u0.y);
        float2 c0 = __half22float2(*(const __half2*)&u1.x);
        float2 c1 = __half22float2(*(const __half2*)&u1.y);
        acc[0] = fmaf(w0, a0.x, fmaf(w1, c0.x, acc[0]));
        acc[1] = fmaf(w0, a0.y, fmaf(w1, c0.y, acc[1]));
        acc[2] = fmaf(w0, a1.x, fmaf(w1, c1.x, acc[2]));
        acc[3] = fmaf(w0, a1.y, fmaf(w1, c1.y, acc[3]));
    }
    if (j < e) {
        int2 e0 = edges[j];
        float w0 = __int_as_float(e0.y);
        uint2 u0 = *(const uint2*)(src + (size_t)e0.x * D + lane * 4);
        float2 a0 = __half22float2(*(const __half2*)&u0.x);
        float2 a1 = __half22float2(*(const __half2*)&u0.y);
        acc[0] = fmaf(w0, a0.x, acc[0]);
        acc[1] = fmaf(w0, a0.y, acc[1]);
        acc[2] = fmaf(w0, a1.x, acc[2]);
        acc[3] = fmaf(w0, a1.y, acc[3]);
    }

    #pragma unroll
    for (int v = 0; v < 4; v++) acc[v] = fmaxf(acc[v], 0.f);
    __half2 h0 = __floats2half2_rn(acc[0], acc[1]);
    __half2 h1 = __floats2half2_rn(acc[2], acc[3]);
    uint2 u;
    u.x = *(uint32_t*)&h0; u.y = *(uint32_t*)&h1;
    *(uint2*)(dst + (size_t)row * D + lane * 4) = u;
}

// ---------------------------------------------------------------------------
// SpMM2: warp per row, D=64 fp16 payload; dst = bias + sum in fp32.
// ---------------------------------------------------------------------------
__global__ void csr_spmm_h_f_kernel(const int* __restrict__ rowptr,
                                    const int2* __restrict__ edges,
                                    const __half* __restrict__ src,
                                    const float* __restrict__ bias,
                                    float* __restrict__ dst, int N) {
    constexpr int D = 64;
    const int lane = threadIdx.x & 31;
    const int row  = blockIdx.x * (blockDim.x >> 5) + (threadIdx.x >> 5);
    if (row >= N) return;

    const int s = rowptr[row];
    const int e = rowptr[row + 1];

    float acc[2];
    acc[0] = bias[lane * 2 + 0];
    acc[1] = bias[lane * 2 + 1];

    int j = s;
    for (; j + 2 <= e; j += 2) {
        int2 e0 = edges[j], e1 = edges[j + 1];
        float w0 = __int_as_float(e0.y), w1 = __int_as_float(e1.y);
        float2 a0 = __half22float2(*(const __half2*)(src + (size_t)e0.x * D + lane * 2));
        float2 c0 = __half22float2(*(const __half2*)(src + (size_t)e1.x * D + lane * 2));
        acc[0] = fmaf(w0, a0.x, fmaf(w1, c0.x, acc[0]));
        acc[1] = fmaf(w0, a0.y, fmaf(w1, c0.y, acc[1]));
    }
    if (j < e) {
        int2 e0 = edges[j];
        float w0 = __int_as_float(e0.y);
        float2 a0 = __half22float2(*(const __half2*)(src + (size_t)e0.x * D + lane * 2));
        acc[0] = fmaf(w0, a0.x, acc[0]);
        acc[1] = fmaf(w0, a0.y, acc[1]);
    }

    *(float2*)(dst + (size_t)row * D + lane * 2) = make_float2(acc[0], acc[1]);
}

// ---------------------------------------------------------------------------
extern "C" void kernel_launch(void* const* d_in, const int* in_sizes, int n_in,
                              void* d_out, int out_size) {
    const float* x  = (const float*)d_in[0];
    const int*   ei = (const int*)d_in[1];     // [2, E] int32
    const float* ew = (const float*)d_in[2];
    const float* W1 = (const float*)d_in[3];
    const float* b1 = (const float*)d_in[4];
    const float* W2 = (const float*)d_in[5];
    const float* b2 = (const float*)d_in[6];
    float* out = (float*)d_out;

    const int M = in_sizes[0] / IN_DIM;   // 50000
    const int E = in_sizes[2];            // 1600000

    __half *S1, *H, *S2;
    int *rowptr, *rowaux;
    int2 *edges;
    cudaGetSymbolAddress((void**)&S1, g_S1);
    cudaGetSymbolAddress((void**)&H,  g_H);
    cudaGetSymbolAddress((void**)&S2, g_S2);
    cudaGetSymbolAddress((void**)&rowptr, g_rowptr);
    cudaGetSymbolAddress((void**)&rowaux, g_rowaux);
    cudaGetSymbolAddress((void**)&edges,  g_edges);

    const int* e_rows = ei;
    const int* e_cols = ei + E;

    static cudaStream_t s_build = nullptr;
    static cudaEvent_t  ev_fork = nullptr, ev_join = nullptr;
    if (s_build == nullptr) {
        cudaStreamCreateWithFlags(&s_build, cudaStreamNonBlocking);
        cudaEventCreateWithFlags(&ev_fork, cudaEventDisableTiming);
        cudaEventCreateWithFlags(&ev_join, cudaEventDisableTiming);
    }

    // ---- fork: CSR build on side stream, GEMM1 on main ----
    cudaEventRecord(ev_fork, 0);
    cudaStreamWaitEvent(s_build, ev_fork, 0);

    const int Epairs = (E + 1) / 2;
    zero_counts_kernel<<<(M + 255) / 256, 256, 0, s_build>>>(rowaux, M);
    hist_kernel<<<(Epairs + 255) / 256, 256, 0, s_build>>>(e_rows, rowaux, E);
    scan_kernel<<<1, 1024, 0, s_build>>>(rowaux, rowptr, M, E);
    scatter_kernel<<<(Epairs + 255) / 256, 256, 0, s_build>>>(e_rows, e_cols, ew,
                                                              rowaux, edges, E);
    cudaEventRecord(ev_join, s_build);

    // GEMM1: S1 = x @ W1 (fp16 mma) — concurrent with CSR build
    gemm1_mma_f16<<<(M + 127) / 128, 256>>>(x, W1, S1, M);

    // ---- join ----
    cudaStreamWaitEvent(0, ev_join, 0);

    // SpMM1: H = relu(A @ S1 + b1), fp16 out
    csr_spmm_h_relu_kernel<<<(M + 7) / 8, 256>>>(rowptr, edges, S1, b1, H, M);

    // GEMM2: S2 = H @ W2 (fp16 mma)
    gemm2_mma_f16<<<(M + 127) / 128, 256>>>(H, W2, S2, M);

    // SpMM2: out = A @ S2 + b2 (fp32 out)
    csr_spmm_h_f_kernel<<<(M + 7) / 8, 256>>>(rowptr, edges, S2, b2, out, M);
}